// round 14
// baseline (speedup 1.0000x reference)
#include <cuda_runtime.h>
#include <cuda_bf16.h>
#include <cstdint>

#define Bsz   32
#define Cdim  128
#define Hdim  112
#define Wdim  112
#define Mwin  7
#define Nwin  49
#define NHw   16
#define NWIMG 256
#define NWTOT 8192
#define HEADS 4
#define DHEAD 32
#define SHIFT 3
#define NTOK  (NWTOT * Nwin)          // 401408
#define QSCALE 0.17677669529663687f   // 1/sqrt(32)

// ---------------- scratch (device globals; no allocation) ----------------
__device__ __nv_bfloat16 g_win [(size_t)NTOK * 128];   // LN+shifted tokens (bf16)
__device__ __nv_bfloat16 g_qkv [(size_t)NTOK * 384];   // QKV (bf16, Q pre-scaled)
__device__ __nv_bfloat16 g_owin[(size_t)NTOK * 128];   // proj output (bf16, bias added)
__device__ __nv_bfloat16 g_wqkv [384 * 128];           // bf16 weights [j][k]
__device__ __nv_bfloat16 g_wproj[128 * 128];
__device__ __nv_bfloat16 g_cmb  [(size_t)NWIMG * HEADS * 64 * 56];  // bias+mask combined

// ---------------- helpers ----------------
__device__ __forceinline__ uint32_t smem_u32(const void* p) {
    uint32_t a;
    asm("{ .reg .u64 t; cvta.to.shared.u64 t, %1; cvt.u32.u64 %0, t; }" : "=r"(a) : "l"(p));
    return a;
}
__device__ __forceinline__ void ldm_x4(uint32_t r[4], uint32_t addr) {
    asm volatile("ldmatrix.sync.aligned.m8n8.x4.shared.b16 {%0,%1,%2,%3}, [%4];"
        : "=r"(r[0]), "=r"(r[1]), "=r"(r[2]), "=r"(r[3]) : "r"(addr));
}
__device__ __forceinline__ void ldm_x4_t(uint32_t r[4], uint32_t addr) {
    asm volatile("ldmatrix.sync.aligned.m8n8.x4.trans.shared.b16 {%0,%1,%2,%3}, [%4];"
        : "=r"(r[0]), "=r"(r[1]), "=r"(r[2]), "=r"(r[3]) : "r"(addr));
}
__device__ __forceinline__ void mma_bf16(float c[4], const uint32_t a[4],
                                         uint32_t b0, uint32_t b1) {
    asm volatile("mma.sync.aligned.m16n8k16.row.col.f32.bf16.bf16.f32 "
        "{%0,%1,%2,%3}, {%4,%5,%6,%7}, {%8,%9}, {%0,%1,%2,%3};"
        : "+f"(c[0]), "+f"(c[1]), "+f"(c[2]), "+f"(c[3])
        : "r"(a[0]), "r"(a[1]), "r"(a[2]), "r"(a[3]), "r"(b0), "r"(b1));
}
__device__ __forceinline__ uint32_t pack_bf16x2(float a, float b) {
    __nv_bfloat162 t = __floats2bfloat162_rn(a, b);
    return *(uint32_t*)&t;
}

#define LDAB 272          // GEMM smem row stride in bytes (136 bf16)
#define TILE_B 34816      // 128 * 272

// ---------------- K0: weights bf16 + combined bias+mask, one launch ----------------
#define PREP_N (384 * 128 + 128 * 128)
#define CMB_N  (NWIMG * HEADS * 64 * 56)
__global__ void prep_cmb_kernel(const float* __restrict__ qkv_w,
                                const float* __restrict__ proj_w,
                                const float* __restrict__ attn_mask,
                                const float* __restrict__ bias_table,
                                const int*   __restrict__ rel_index) {
    int i = blockIdx.x * blockDim.x + threadIdx.x;
    if (i < PREP_N) {
        if (i < 384 * 128) g_wqkv[i] = __float2bfloat16_rn(qkv_w[i]);
        else               g_wproj[i - 384 * 128] = __float2bfloat16_rn(proj_w[i - 384 * 128]);
        return;
    }
    i -= PREP_N;
    if (i >= CMB_N) return;
    int m = i % 56; int t = i / 56;
    int n = t & 63; t >>= 6;
    int hd = t & 3; int wimg = t >> 2;
    float v;
    if (n >= Nwin)      v = 0.f;
    else if (m >= Nwin) v = -30000.f;
    else v = bias_table[rel_index[n * Nwin + m] * HEADS + hd]
           + attn_mask[((size_t)wimg * Nwin + n) * Nwin + m];
    g_cmb[i] = __float2bfloat16_rn(v);
}

// ---------------- K1: LayerNorm + shift + window partition (bf16 out) ----------------
#define RS 132
__global__ void ln_window_kernel(const float* __restrict__ x,
                                 const float* __restrict__ nw,
                                 const float* __restrict__ nb) {
    __shared__ float s[56 * RS];   // [w][c]
    int h = blockIdx.x, half = blockIdx.y, b = blockIdx.z;
    int w0 = half * 56;
    int tid = threadIdx.x;

    const float* xp = x + (size_t)b * Cdim * (Hdim * Wdim) + (size_t)h * Wdim + w0;
    for (int e = tid; e < 128 * 14; e += 256) {
        int c = e / 14, w4 = (e % 14) * 4;
        float4 v = *(const float4*)(xp + (size_t)c * (Hdim * Wdim) + w4);
        s[(w4 + 0) * RS + c] = v.x;
        s[(w4 + 1) * RS + c] = v.y;
        s[(w4 + 2) * RS + c] = v.z;
        s[(w4 + 3) * RS + c] = v.w;
    }
    __syncthreads();

    int warp = tid >> 5, lane = tid & 31;
    for (int wl = warp; wl < 56; wl += 8) {
        float4 v = *(const float4*)&s[wl * RS + lane * 4];
        float sum = v.x + v.y + v.z + v.w;
        float sq  = v.x * v.x + v.y * v.y + v.z * v.z + v.w * v.w;
        #pragma unroll
        for (int o = 16; o > 0; o >>= 1) {
            sum += __shfl_xor_sync(0xffffffff, sum, o);
            sq  += __shfl_xor_sync(0xffffffff, sq,  o);
        }
        float mu  = sum * (1.0f / 128.0f);
        float var = sq * (1.0f / 128.0f) - mu * mu;
        float inv = rsqrtf(var + 1e-5f);

        int c0 = lane * 4;
        float4 g  = *(const float4*)&nw[c0];
        float4 be = *(const float4*)&nb[c0];
        __align__(8) __nv_bfloat162 o2[2];
        o2[0] = __floats2bfloat162_rn((v.x - mu) * inv * g.x + be.x,
                                      (v.y - mu) * inv * g.y + be.y);
        o2[1] = __floats2bfloat162_rn((v.z - mu) * inv * g.z + be.z,
                                      (v.w - mu) * inv * g.w + be.w);

        int ws = w0 + wl;
        int hd = h - SHIFT;  if (hd < 0) hd += Hdim;
        int wd = ws - SHIFT; if (wd < 0) wd += Wdim;
        int wi = b * NWIMG + (hd / Mwin) * NHw + (wd / Mwin);
        int n  = (hd % Mwin) * Mwin + (wd % Mwin);
        *(uint2*)&g_win[((size_t)wi * Nwin + n) * 128 + c0] = *(uint2*)o2;
    }
}

// ---------------- K2: QKV GEMM (mma.sync bf16), 8 warps of 64x32 ----------------
#define GQ_SMEM (3 * TILE_B)
__global__ __launch_bounds__(256, 2) void gemm_qkv_kernel(const float* __restrict__ qkv_b) {
    extern __shared__ __align__(16) char sm[];
    char* sA = sm;
    char* sB = sm + TILE_B;
    char* sC = sm + 2 * TILE_B;

    int tid = threadIdx.x, wid = tid >> 5, lane = tid & 31;
    int warp_m = wid >> 2, warp_n = wid & 3;

    const __nv_bfloat16* A = g_win + (size_t)blockIdx.x * (128 * 128);
    for (int e = tid; e < 2048; e += 256) {
        int r = e >> 4, j = e & 15;
        *(uint4*)(sA + r * LDAB + j * 16) = *(const uint4*)(A + r * 128 + j * 8);
    }
    for (int e = tid; e < 2048; e += 256) {
        int r = e >> 4, j = e & 15;
        *(uint4*)(sB + r * LDAB + j * 16) = *(const uint4*)(g_wqkv + r * 128 + j * 8);
    }
    __syncthreads();

    uint32_t pA = smem_u32(sA) + (uint32_t)((warp_m * 64 + (lane & 15)) * LDAB + ((lane >> 4) << 4));
    uint32_t pB = smem_u32(sB) + (uint32_t)((warp_n * 32 + (lane & 15)) * LDAB + ((lane >> 4) << 4));
    size_t row0 = (size_t)blockIdx.x * 128;
    int g = lane >> 2, tg = lane & 3;

    #pragma unroll 1
    for (int jb = 0; jb < 3; ++jb) {
        float c[4][4][4];
        #pragma unroll
        for (int mt = 0; mt < 4; ++mt)
            #pragma unroll
            for (int nt = 0; nt < 4; ++nt)
                #pragma unroll
                for (int q = 0; q < 4; ++q) c[mt][nt][q] = 0.f;

        #pragma unroll
        for (int k0 = 0; k0 < 128; k0 += 16) {
            uint32_t a[4][4], bb[2][4];
            #pragma unroll
            for (int mt = 0; mt < 4; ++mt)
                ldm_x4(a[mt], pA + mt * (16 * LDAB) + k0 * 2);
            #pragma unroll
            for (int p = 0; p < 2; ++p)
                ldm_x4(bb[p], pB + p * (16 * LDAB) + k0 * 2);
            #pragma unroll
            for (int mt = 0; mt < 4; ++mt)
                #pragma unroll
                for (int nt = 0; nt < 4; ++nt)
                    mma_bf16(c[mt][nt], a[mt], bb[nt >> 1][nt & 1], bb[nt >> 1][2 + (nt & 1)]);
        }

        float s = (jb == 0) ? QSCALE : 1.0f;
        #pragma unroll
        for (int nt = 0; nt < 4; ++nt) {
            int col = warp_n * 32 + nt * 8 + 2 * tg;
            float b0v = qkv_b[jb * 128 + col];
            float b1v = qkv_b[jb * 128 + col + 1];
            #pragma unroll
            for (int mt = 0; mt < 4; ++mt) {
                int row = warp_m * 64 + mt * 16 + g;
                __nv_bfloat162 lo = __floats2bfloat162_rn((c[mt][nt][0] + b0v) * s,
                                                          (c[mt][nt][1] + b1v) * s);
                __nv_bfloat162 hi = __floats2bfloat162_rn((c[mt][nt][2] + b0v) * s,
                                                          (c[mt][nt][3] + b1v) * s);
                *(__nv_bfloat162*)(sC + row * LDAB + col * 2) = lo;
                *(__nv_bfloat162*)(sC + (row + 8) * LDAB + col * 2) = hi;
            }
        }
        __syncthreads();

        if (jb < 2) {
            const __nv_bfloat16* Bn = g_wqkv + (size_t)(jb + 1) * 128 * 128;
            for (int e = tid; e < 2048; e += 256) {
                int r = e >> 4, j = e & 15;
                *(uint4*)(sB + r * LDAB + j * 16) = *(const uint4*)(Bn + r * 128 + j * 8);
            }
        }
        for (int e = tid; e < 2048; e += 256) {
            int r = e >> 4, j = e & 15;
            *(uint4*)(g_qkv + (row0 + r) * 384 + jb * 128 + j * 8) =
                *(uint4*)(sC + r * LDAB + j * 16);
        }
        __syncthreads();
    }
}

// ---------------- K3: fused attention + proj, 2 windows per CTA ----------------
// 512 threads / 16 warps: warp w -> window win=w>>3, (head, half) from w&7.
// smem: two [64][392] regions; wproj staged once into window-0's dead K/V region.
#define AQKV 392
#define WINB (64 * AQKV)                 // bf16 elements per window region
#define ATTN_SMEM (2 * WINB * 2)         // 100352 B -> 2 CTAs/SM (32 warps)
__global__ __launch_bounds__(512, 2) void attn_kernel(const float* __restrict__ proj_b) {
    extern __shared__ __align__(16) __nv_bfloat16 smb[];

    int wp = blockIdx.x, tid = threadIdx.x;
    int warp = tid >> 5, lane = tid & 31;
    int win = warp >> 3, wid = warp & 7;
    int wi = wp * 2 + win, wimg = wi & (NWIMG - 1);
    __nv_bfloat16* sQKV = smb + win * WINB;

    // prologue: both windows
    const __nv_bfloat16* src0 = g_qkv + (size_t)wp * 2 * Nwin * 384;
    for (int e = tid; e < 2 * Nwin * 48; e += 512) {
        int vw = e / (Nwin * 48), r = e % (Nwin * 48);
        int n = r / 48, j = r % 48;
        *(uint4*)&smb[vw * WINB + n * AQKV + j * 8] =
            *(const uint4*)(src0 + ((size_t)vw * Nwin + n) * 384 + j * 8);
    }
    for (int e = tid; e < 2 * 15 * 49; e += 512) {
        int vw = e / (15 * 49), r2 = e % (15 * 49);
        int rr = 49 + r2 / 49, j = r2 % 49;
        *(uint4*)&smb[vw * WINB + rr * AQKV + j * 8] = make_uint4(0, 0, 0, 0);
    }
    __syncthreads();

    int hd = wid & 3, half = wid >> 2;
    int g = lane >> 2, tg = lane & 3;
    uint32_t sq = smem_u32(sQKV);
    int lrow = lane & 15, lsel = (lane >> 4) << 4;
    uint32_t baseQ = sq + (uint32_t)(lrow * (AQKV * 2) + (hd * 32) * 2 + lsel);
    uint32_t baseK = sq + (uint32_t)(lrow * (AQKV * 2) + (128 + hd * 32) * 2 + lsel);
    uint32_t baseV = sq + (uint32_t)(lrow * (AQKV * 2) + (256 + hd * 32) * 2 + lsel);

    const __nv_bfloat162* cm =
        (const __nv_bfloat162*)(g_cmb + (size_t)(wimg * HEADS + hd) * 64 * 56);

    // ---------- phase 1: attention (per window) ----------
    #pragma unroll
    for (int mi = 0; mi < 2; ++mi) {
        int mt = half * 2 + mi;
        uint32_t qf[2][4];
        #pragma unroll
        for (int kt = 0; kt < 2; ++kt)
            ldm_x4(qf[kt], baseQ + (uint32_t)(mt * 16 * (AQKV * 2) + kt * 32));

        int rA = mt * 16 + g, rB = rA + 8;
        float s[7][4];
        #pragma unroll
        for (int nt = 0; nt < 7; ++nt) {
            float2 fa = __bfloat1622float2(cm[(rA * 56 + nt * 8 + 2 * tg) >> 1]);
            float2 fb = __bfloat1622float2(cm[(rB * 56 + nt * 8 + 2 * tg) >> 1]);
            s[nt][0] = fa.x; s[nt][1] = fa.y; s[nt][2] = fb.x; s[nt][3] = fb.y;
        }
        #pragma unroll
        for (int kt = 0; kt < 2; ++kt) {
            #pragma unroll
            for (int ntp = 0; ntp < 4; ++ntp) {
                uint32_t kb[4];
                ldm_x4(kb, baseK + (uint32_t)(ntp * 16 * (AQKV * 2) + kt * 32));
                mma_bf16(s[2 * ntp], qf[kt], kb[0], kb[2]);
                if (ntp < 3) mma_bf16(s[2 * ntp + 1], qf[kt], kb[1], kb[3]);
            }
        }

        // softmax without max subtraction (logits bounded; pads give exp(-3e4)->0)
        float sumA = 0.f, sumB = 0.f;
        #pragma unroll
        for (int nt = 0; nt < 7; ++nt) {
            s[nt][0] = __expf(s[nt][0]); sumA += s[nt][0];
            s[nt][1] = __expf(s[nt][1]); sumA += s[nt][1];
            s[nt][2] = __expf(s[nt][2]); sumB += s[nt][2];
            s[nt][3] = __expf(s[nt][3]); sumB += s[nt][3];
        }
        sumA += __shfl_xor_sync(0xffffffff, sumA, 1);
        sumA += __shfl_xor_sync(0xffffffff, sumA, 2);
        sumB += __shfl_xor_sync(0xffffffff, sumB, 1);
        sumB += __shfl_xor_sync(0xffffffff, sumB, 2);
        float invA = 1.0f / sumA, invB = 1.0f / sumB;
        #pragma unroll
        for (int nt = 0; nt < 7; ++nt) {
            s[nt][0] *= invA; s[nt][1] *= invA;
            s[nt][2] *= invB; s[nt][3] *= invB;
        }

        uint32_t pf[4][4];
        #pragma unroll
        for (int kt = 0; kt < 4; ++kt) {
            int nt0 = 2 * kt, nt1 = 2 * kt + 1;
            pf[kt][0] = pack_bf16x2(s[nt0][0], s[nt0][1]);
            pf[kt][1] = pack_bf16x2(s[nt0][2], s[nt0][3]);
            if (nt1 < 7) {
                pf[kt][2] = pack_bf16x2(s[nt1][0], s[nt1][1]);
                pf[kt][3] = pack_bf16x2(s[nt1][2], s[nt1][3]);
            } else {
                pf[kt][2] = 0u; pf[kt][3] = 0u;
            }
        }

        float o[4][4];
        #pragma unroll
        for (int dt = 0; dt < 4; ++dt)
            #pragma unroll
            for (int q = 0; q < 4; ++q) o[dt][q] = 0.f;
        #pragma unroll
        for (int kt = 0; kt < 4; ++kt) {
            uint32_t vb[2][4];
            #pragma unroll
            for (int dp = 0; dp < 2; ++dp)
                ldm_x4_t(vb[dp], baseV + (uint32_t)(kt * 16 * (AQKV * 2) + dp * 32));
            #pragma unroll
            for (int dt = 0; dt < 4; ++dt)
                mma_bf16(o[dt], pf[kt], vb[dt >> 1][2 * (dt & 1)], vb[dt >> 1][2 * (dt & 1) + 1]);
        }

        // store O into own window's dead Q slice — race-free
        #pragma unroll
        for (int dt = 0; dt < 4; ++dt) {
            int col = hd * 32 + dt * 8 + 2 * tg;
            *(__nv_bfloat162*)&sQKV[rA * AQKV + col] = __floats2bfloat162_rn(o[dt][0], o[dt][1]);
            *(__nv_bfloat162*)&sQKV[rB * AQKV + col] = __floats2bfloat162_rn(o[dt][2], o[dt][3]);
        }
    }
    __syncthreads();   // all O in smem; K/V regions now dead

    // ---------- phase 2: proj (wproj staged ONCE, window-0 K/V region) ----------
    for (int e = tid; e < 2048; e += 512) {
        int j = e >> 4, kq = e & 15;
        *(uint4*)&smb[(j & 63) * AQKV + 128 + ((j >> 6) << 7) + kq * 8] =
            *(const uint4*)(g_wproj + j * 128 + kq * 8);
    }
    __syncthreads();

    int warp_m = half, warp_n = hd;   // per-window 2 x 4 warp grid, m32 x n32
    uint32_t sq0 = smem_u32(smb);
    uint32_t baseA2 = sq + (uint32_t)((warp_m * 32 + lrow) * (AQKV * 2) + lsel);
    uint32_t baseB2 = sq0 + (uint32_t)((((warp_n * 32) & 63) + lrow) * (AQKV * 2)
                                       + (128 + ((warp_n >> 1) << 7)) * 2 + lsel);

    float pc[2][4][4];
    #pragma unroll
    for (int mt2 = 0; mt2 < 2; ++mt2)
        #pragma unroll
        for (int j = 0; j < 4; ++j)
            #pragma unroll
            for (int q = 0; q < 4; ++q) pc[mt2][j][q] = 0.f;

    #pragma unroll
    for (int k0 = 0; k0 < 128; k0 += 16) {
        uint32_t af[2][4], bbp[2][4];
        #pragma unroll
        for (int mt2 = 0; mt2 < 2; ++mt2)
            ldm_x4(af[mt2], baseA2 + (uint32_t)(mt2 * 16 * (AQKV * 2) + k0 * 2));
        #pragma unroll
        for (int p = 0; p < 2; ++p)
            ldm_x4(bbp[p], baseB2 + (uint32_t)(p * 16 * (AQKV * 2) + k0 * 2));
        #pragma unroll
        for (int mt2 = 0; mt2 < 2; ++mt2)
            #pragma unroll
            for (int p = 0; p < 2; ++p) {
                mma_bf16(pc[mt2][2 * p],     af[mt2], bbp[p][0], bbp[p][2]);
                mma_bf16(pc[mt2][2 * p + 1], af[mt2], bbp[p][1], bbp[p][3]);
            }
    }

    __nv_bfloat16* ow = g_owin + (size_t)wi * Nwin * 128;
    #pragma unroll
    for (int j = 0; j < 4; ++j) {
        int col = warp_n * 32 + j * 8 + 2 * tg;
        float b0v = proj_b[col], b1v = proj_b[col + 1];
        #pragma unroll
        for (int mt2 = 0; mt2 < 2; ++mt2) {
            int row = warp_m * 32 + mt2 * 16 + g;
            if (row < Nwin)
                *(__nv_bfloat162*)&ow[(size_t)row * 128 + col] =
                    __floats2bfloat162_rn(pc[mt2][j][0] + b0v, pc[mt2][j][1] + b1v);
            if (row + 8 < Nwin)
                *(__nv_bfloat162*)&ow[(size_t)(row + 8) * 128 + col] =
                    __floats2bfloat162_rn(pc[mt2][j][2] + b0v, pc[mt2][j][3] + b1v);
        }
    }
}

// ---------------- K5: window reverse + unshift + residual (vectorized) ----------------
__global__ void reverse_kernel(const float* __restrict__ x,
                               float* __restrict__ out) {
    __shared__ float s2[56 * 132];   // [wl][c]
    int h = blockIdx.x, half = blockIdx.y, b = blockIdx.z;
    int w0 = half * 56;
    int tid = threadIdx.x;

    int h2 = h - SHIFT; if (h2 < 0) h2 += Hdim;
    int whh = h2 / Mwin, rr = h2 % Mwin;

    for (int e = tid; e < 56 * 16; e += 256) {
        int wl = e >> 4, j = e & 15;
        int w = w0 + wl;
        int w2 = w - SHIFT; if (w2 < 0) w2 += Wdim;
        int wi = b * NWIMG + whh * NHw + (w2 / Mwin);
        int n  = rr * Mwin + (w2 % Mwin);
        uint4 raw = *(const uint4*)&g_owin[((size_t)wi * Nwin + n) * 128 + j * 8];
        __nv_bfloat162 p[4]; *(uint4*)p = raw;
        float2 f0 = __bfloat1622float2(p[0]);
        float2 f1 = __bfloat1622float2(p[1]);
        float2 f2 = __bfloat1622float2(p[2]);
        float2 f3 = __bfloat1622float2(p[3]);
        *(float4*)&s2[wl * 132 + j * 8]     = make_float4(f0.x, f0.y, f1.x, f1.y);
        *(float4*)&s2[wl * 132 + j * 8 + 4] = make_float4(f2.x, f2.y, f3.x, f3.y);
    }
    __syncthreads();

    size_t base = (size_t)b * Cdim * (Hdim * Wdim) + (size_t)h * Wdim + w0;
    for (int e = tid; e < 128 * 14; e += 256) {
        int c = e / 14, wq = (e % 14) * 4;
        size_t gi = base + (size_t)c * (Hdim * Wdim) + wq;
        float4 xv = *(const float4*)&x[gi];
        float4 o;
        o.x = xv.x + s2[(wq + 0) * 132 + c];
        o.y = xv.y + s2[(wq + 1) * 132 + c];
        o.z = xv.z + s2[(wq + 2) * 132 + c];
        o.w = xv.w + s2[(wq + 3) * 132 + c];
        *(float4*)&out[gi] = o;
    }
}

// ---------------- launch ----------------
extern "C" void kernel_launch(void* const* d_in, const int* in_sizes, int n_in,
                              void* d_out, int out_size) {
    const float* x          = (const float*)d_in[0];
    const float* norm_w     = (const float*)d_in[1];
    const float* norm_b     = (const float*)d_in[2];
    const float* qkv_w      = (const float*)d_in[3];
    const float* qkv_b      = (const float*)d_in[4];
    const float* proj_w     = (const float*)d_in[5];
    const float* proj_b     = (const float*)d_in[6];
    const float* bias_table = (const float*)d_in[7];
    const int*   rel_index  = (const int*)  d_in[8];
    const float* attn_mask  = (const float*)d_in[9];
    float* out = (float*)d_out;

    cudaFuncSetAttribute(gemm_qkv_kernel, cudaFuncAttributeMaxDynamicSharedMemorySize, GQ_SMEM);
    cudaFuncSetAttribute(attn_kernel,     cudaFuncAttributeMaxDynamicSharedMemorySize, ATTN_SMEM);

    int pc_total = PREP_N + CMB_N;
    prep_cmb_kernel<<<(pc_total + 255) / 256, 256>>>(qkv_w, proj_w, attn_mask,
                                                     bias_table, rel_index);
    ln_window_kernel<<<dim3(Hdim, 2, Bsz), 256>>>(x, norm_w, norm_b);
    gemm_qkv_kernel<<<NTOK / 128, 256, GQ_SMEM>>>(qkv_b);
    attn_kernel<<<NWTOT / 2, 512, ATTN_SMEM>>>(proj_b);
    reverse_kernel<<<dim3(Hdim, 2, Bsz), 256>>>(x, out);
}

// round 16
// speedup vs baseline: 1.4246x; 1.4246x over previous
#include <cuda_runtime.h>
#include <cuda_bf16.h>
#include <cstdint>

#define Bsz   32
#define Cdim  128
#define Hdim  112
#define Wdim  112
#define Mwin  7
#define Nwin  49
#define NHw   16
#define NWIMG 256
#define NWTOT 8192
#define HEADS 4
#define DHEAD 32
#define SHIFT 3
#define NTOK  (NWTOT * Nwin)          // 401408
#define QSCALE 0.17677669529663687f   // 1/sqrt(32)

// ---------------- scratch (device globals; no allocation) ----------------
__device__ __nv_bfloat16 g_win [(size_t)NTOK * 128];   // LN+shifted tokens (bf16)
__device__ __nv_bfloat16 g_qkv [(size_t)NTOK * 384];   // QKV (bf16, Q pre-scaled)
__device__ __nv_bfloat16 g_owin[(size_t)NTOK * 128];   // proj output (bf16, bias added)
__device__ __nv_bfloat16 g_wqkv [384 * 128];           // bf16 weights [j][k]
__device__ __nv_bfloat16 g_wproj[128 * 128];
__device__ __nv_bfloat16 g_cmb  [(size_t)NWIMG * HEADS * 64 * 56];  // bias+mask combined

// ---------------- helpers ----------------
__device__ __forceinline__ uint32_t smem_u32(const void* p) {
    uint32_t a;
    asm("{ .reg .u64 t; cvta.to.shared.u64 t, %1; cvt.u32.u64 %0, t; }" : "=r"(a) : "l"(p));
    return a;
}
__device__ __forceinline__ void ldm_x4(uint32_t r[4], uint32_t addr) {
    asm volatile("ldmatrix.sync.aligned.m8n8.x4.shared.b16 {%0,%1,%2,%3}, [%4];"
        : "=r"(r[0]), "=r"(r[1]), "=r"(r[2]), "=r"(r[3]) : "r"(addr));
}
__device__ __forceinline__ void ldm_x4_t(uint32_t r[4], uint32_t addr) {
    asm volatile("ldmatrix.sync.aligned.m8n8.x4.trans.shared.b16 {%0,%1,%2,%3}, [%4];"
        : "=r"(r[0]), "=r"(r[1]), "=r"(r[2]), "=r"(r[3]) : "r"(addr));
}
__device__ __forceinline__ void mma_bf16(float c[4], const uint32_t a[4],
                                         uint32_t b0, uint32_t b1) {
    asm volatile("mma.sync.aligned.m16n8k16.row.col.f32.bf16.bf16.f32 "
        "{%0,%1,%2,%3}, {%4,%5,%6,%7}, {%8,%9}, {%0,%1,%2,%3};"
        : "+f"(c[0]), "+f"(c[1]), "+f"(c[2]), "+f"(c[3])
        : "r"(a[0]), "r"(a[1]), "r"(a[2]), "r"(a[3]), "r"(b0), "r"(b1));
}
__device__ __forceinline__ uint32_t pack_bf16x2(float a, float b) {
    __nv_bfloat162 t = __floats2bfloat162_rn(a, b);
    return *(uint32_t*)&t;
}

#define LDAB 272          // GEMM smem row stride in bytes (136 bf16)
#define TILE_B 34816      // 128 * 272

#define PREP_N (384 * 128 + 128 * 128)
#define CMB_N  (NWIMG * HEADS * 64 * 56)
#define PC_TOTAL (PREP_N + CMB_N)                 // 1900544
#define PC_CTAS  ((PC_TOTAL + 255) / 256)         // 7424
#define PC_ZSL   ((PC_CTAS + Hdim * 2 - 1) / (Hdim * 2))   // 34 extra z-slices

// ---------------- K1: LayerNorm+window (z < Bsz)  |  prep+cmb (z >= Bsz) ----------------
#define RS 132
__global__ void ln_prep_kernel(const float* __restrict__ x,
                               const float* __restrict__ nw,
                               const float* __restrict__ nb,
                               const float* __restrict__ qkv_w,
                               const float* __restrict__ proj_w,
                               const float* __restrict__ attn_mask,
                               const float* __restrict__ bias_table,
                               const int*   __restrict__ rel_index) {
    __shared__ float s[56 * RS];   // [w][c]
    int tid = threadIdx.x;

    if (blockIdx.z >= Bsz) {
        // ---- prep + cmb branch (exits before any barrier) ----
        int pb = (blockIdx.z - Bsz) * (Hdim * 2) + blockIdx.x * 2 + blockIdx.y;
        int i = pb * 256 + tid;
        if (i < PREP_N) {
            if (i < 384 * 128) g_wqkv[i] = __float2bfloat16_rn(qkv_w[i]);
            else               g_wproj[i - 384 * 128] = __float2bfloat16_rn(proj_w[i - 384 * 128]);
            return;
        }
        i -= PREP_N;
        if (i >= CMB_N) return;
        int m = i % 56; int t = i / 56;
        int n = t & 63; t >>= 6;
        int hd = t & 3; int wimg = t >> 2;
        float v;
        if (n >= Nwin)      v = 0.f;
        else if (m >= Nwin) v = -30000.f;
        else v = bias_table[rel_index[n * Nwin + m] * HEADS + hd]
               + attn_mask[((size_t)wimg * Nwin + n) * Nwin + m];
        g_cmb[i] = __float2bfloat16_rn(v);
        return;
    }

    // ---- LayerNorm branch ----
    int h = blockIdx.x, half = blockIdx.y, b = blockIdx.z;
    int w0 = half * 56;

    const float* xp = x + (size_t)b * Cdim * (Hdim * Wdim) + (size_t)h * Wdim + w0;
    for (int e = tid; e < 128 * 14; e += 256) {
        int c = e / 14, w4 = (e % 14) * 4;
        float4 v = *(const float4*)(xp + (size_t)c * (Hdim * Wdim) + w4);
        s[(w4 + 0) * RS + c] = v.x;
        s[(w4 + 1) * RS + c] = v.y;
        s[(w4 + 2) * RS + c] = v.z;
        s[(w4 + 3) * RS + c] = v.w;
    }
    __syncthreads();

    int warp = tid >> 5, lane = tid & 31;
    for (int wl = warp; wl < 56; wl += 8) {
        float4 v = *(const float4*)&s[wl * RS + lane * 4];
        float sum = v.x + v.y + v.z + v.w;
        float sq  = v.x * v.x + v.y * v.y + v.z * v.z + v.w * v.w;
        #pragma unroll
        for (int o = 16; o > 0; o >>= 1) {
            sum += __shfl_xor_sync(0xffffffff, sum, o);
            sq  += __shfl_xor_sync(0xffffffff, sq,  o);
        }
        float mu  = sum * (1.0f / 128.0f);
        float var = sq * (1.0f / 128.0f) - mu * mu;
        float inv = rsqrtf(var + 1e-5f);

        int c0 = lane * 4;
        float4 g  = *(const float4*)&nw[c0];
        float4 be = *(const float4*)&nb[c0];
        __align__(8) __nv_bfloat162 o2[2];
        o2[0] = __floats2bfloat162_rn((v.x - mu) * inv * g.x + be.x,
                                      (v.y - mu) * inv * g.y + be.y);
        o2[1] = __floats2bfloat162_rn((v.z - mu) * inv * g.z + be.z,
                                      (v.w - mu) * inv * g.w + be.w);

        int ws = w0 + wl;
        int hd = h - SHIFT;  if (hd < 0) hd += Hdim;
        int wd = ws - SHIFT; if (wd < 0) wd += Wdim;
        int wi = b * NWIMG + (hd / Mwin) * NHw + (wd / Mwin);
        int n  = (hd % Mwin) * Mwin + (wd % Mwin);
        *(uint2*)&g_win[((size_t)wi * Nwin + n) * 128 + c0] = *(uint2*)o2;
    }
}

// ---------------- K2: QKV GEMM (mma.sync bf16), 8 warps of 64x32 ----------------
#define GQ_SMEM (3 * TILE_B)
__global__ __launch_bounds__(256, 2) void gemm_qkv_kernel(const float* __restrict__ qkv_b) {
    extern __shared__ __align__(16) char sm[];
    char* sA = sm;
    char* sB = sm + TILE_B;
    char* sC = sm + 2 * TILE_B;

    int tid = threadIdx.x, wid = tid >> 5, lane = tid & 31;
    int warp_m = wid >> 2, warp_n = wid & 3;

    const __nv_bfloat16* A = g_win + (size_t)blockIdx.x * (128 * 128);
    for (int e = tid; e < 2048; e += 256) {
        int r = e >> 4, j = e & 15;
        *(uint4*)(sA + r * LDAB + j * 16) = *(const uint4*)(A + r * 128 + j * 8);
    }
    for (int e = tid; e < 2048; e += 256) {
        int r = e >> 4, j = e & 15;
        *(uint4*)(sB + r * LDAB + j * 16) = *(const uint4*)(g_wqkv + r * 128 + j * 8);
    }
    __syncthreads();

    uint32_t pA = smem_u32(sA) + (uint32_t)((warp_m * 64 + (lane & 15)) * LDAB + ((lane >> 4) << 4));
    uint32_t pB = smem_u32(sB) + (uint32_t)((warp_n * 32 + (lane & 15)) * LDAB + ((lane >> 4) << 4));
    size_t row0 = (size_t)blockIdx.x * 128;
    int g = lane >> 2, tg = lane & 3;

    #pragma unroll 1
    for (int jb = 0; jb < 3; ++jb) {
        float c[4][4][4];
        #pragma unroll
        for (int mt = 0; mt < 4; ++mt)
            #pragma unroll
            for (int nt = 0; nt < 4; ++nt)
                #pragma unroll
                for (int q = 0; q < 4; ++q) c[mt][nt][q] = 0.f;

        #pragma unroll
        for (int k0 = 0; k0 < 128; k0 += 16) {
            uint32_t a[4][4], bb[2][4];
            #pragma unroll
            for (int mt = 0; mt < 4; ++mt)
                ldm_x4(a[mt], pA + mt * (16 * LDAB) + k0 * 2);
            #pragma unroll
            for (int p = 0; p < 2; ++p)
                ldm_x4(bb[p], pB + p * (16 * LDAB) + k0 * 2);
            #pragma unroll
            for (int mt = 0; mt < 4; ++mt)
                #pragma unroll
                for (int nt = 0; nt < 4; ++nt)
                    mma_bf16(c[mt][nt], a[mt], bb[nt >> 1][nt & 1], bb[nt >> 1][2 + (nt & 1)]);
        }

        float s = (jb == 0) ? QSCALE : 1.0f;
        #pragma unroll
        for (int nt = 0; nt < 4; ++nt) {
            int col = warp_n * 32 + nt * 8 + 2 * tg;
            float b0v = qkv_b[jb * 128 + col];
            float b1v = qkv_b[jb * 128 + col + 1];
            #pragma unroll
            for (int mt = 0; mt < 4; ++mt) {
                int row = warp_m * 64 + mt * 16 + g;
                __nv_bfloat162 lo = __floats2bfloat162_rn((c[mt][nt][0] + b0v) * s,
                                                          (c[mt][nt][1] + b1v) * s);
                __nv_bfloat162 hi = __floats2bfloat162_rn((c[mt][nt][2] + b0v) * s,
                                                          (c[mt][nt][3] + b1v) * s);
                *(__nv_bfloat162*)(sC + row * LDAB + col * 2) = lo;
                *(__nv_bfloat162*)(sC + (row + 8) * LDAB + col * 2) = hi;
            }
        }
        __syncthreads();

        if (jb < 2) {
            const __nv_bfloat16* Bn = g_wqkv + (size_t)(jb + 1) * 128 * 128;
            for (int e = tid; e < 2048; e += 256) {
                int r = e >> 4, j = e & 15;
                *(uint4*)(sB + r * LDAB + j * 16) = *(const uint4*)(Bn + r * 128 + j * 8);
            }
        }
        for (int e = tid; e < 2048; e += 256) {
            int r = e >> 4, j = e & 15;
            *(uint4*)(g_qkv + (row0 + r) * 384 + jb * 128 + j * 8) =
                *(uint4*)(sC + r * LDAB + j * 16);
        }
        __syncthreads();
    }
}

// ---------------- K3: fused window attention + proj (mma.sync), r13 config ----------------
#define AQKV 392
#define ATTN_SMEM (64 * AQKV * 2)   // 50176 B -> 4 CTAs/SM
__global__ __launch_bounds__(256, 4) void attn_kernel(const float* __restrict__ proj_b) {
    extern __shared__ __align__(16) __nv_bfloat16 smb[];
    __nv_bfloat16* sQKV = smb;

    int wi = blockIdx.x, wimg = wi & (NWIMG - 1), tid = threadIdx.x;
    int wid = tid >> 5, lane = tid & 31;

    const __nv_bfloat16* src = g_qkv + (size_t)wi * Nwin * 384;
    for (int e = tid; e < Nwin * 48; e += 256) {
        int n = e / 48, j = e % 48;
        *(uint4*)&sQKV[n * AQKV + j * 8] = *(const uint4*)(src + n * 384 + j * 8);
    }
    for (int e = tid; e < 15 * 49; e += 256) {
        int r = 49 + e / 49, j = e % 49;
        *(uint4*)&sQKV[r * AQKV + j * 8] = make_uint4(0, 0, 0, 0);
    }
    __syncthreads();

    int hd = wid & 3, half = wid >> 2;
    int g = lane >> 2, tg = lane & 3;
    uint32_t sq = smem_u32(sQKV);
    int lrow = lane & 15, lsel = (lane >> 4) << 4;
    uint32_t baseQ = sq + (uint32_t)(lrow * (AQKV * 2) + (hd * 32) * 2 + lsel);
    uint32_t baseK = sq + (uint32_t)(lrow * (AQKV * 2) + (128 + hd * 32) * 2 + lsel);
    uint32_t baseV = sq + (uint32_t)(lrow * (AQKV * 2) + (256 + hd * 32) * 2 + lsel);

    const __nv_bfloat162* cm =
        (const __nv_bfloat162*)(g_cmb + (size_t)(wimg * HEADS + hd) * 64 * 56);

    // ---------- phase 1: attention ----------
    #pragma unroll
    for (int mi = 0; mi < 2; ++mi) {
        int mt = half * 2 + mi;
        uint32_t qf[2][4];
        #pragma unroll
        for (int kt = 0; kt < 2; ++kt)
            ldm_x4(qf[kt], baseQ + (uint32_t)(mt * 16 * (AQKV * 2) + kt * 32));

        int rA = mt * 16 + g, rB = rA + 8;
        float s[7][4];
        #pragma unroll
        for (int nt = 0; nt < 7; ++nt) {
            float2 fa = __bfloat1622float2(cm[(rA * 56 + nt * 8 + 2 * tg) >> 1]);
            float2 fb = __bfloat1622float2(cm[(rB * 56 + nt * 8 + 2 * tg) >> 1]);
            s[nt][0] = fa.x; s[nt][1] = fa.y; s[nt][2] = fb.x; s[nt][3] = fb.y;
        }
        #pragma unroll
        for (int kt = 0; kt < 2; ++kt) {
            #pragma unroll
            for (int ntp = 0; ntp < 4; ++ntp) {
                uint32_t kb[4];
                ldm_x4(kb, baseK + (uint32_t)(ntp * 16 * (AQKV * 2) + kt * 32));
                mma_bf16(s[2 * ntp], qf[kt], kb[0], kb[2]);
                if (ntp < 3) mma_bf16(s[2 * ntp + 1], qf[kt], kb[1], kb[3]);
            }
        }

        // softmax without max subtraction (logits bounded; pads -> exp(-3e4)=0)
        float sumA = 0.f, sumB = 0.f;
        #pragma unroll
        for (int nt = 0; nt < 7; ++nt) {
            s[nt][0] = __expf(s[nt][0]); sumA += s[nt][0];
            s[nt][1] = __expf(s[nt][1]); sumA += s[nt][1];
            s[nt][2] = __expf(s[nt][2]); sumB += s[nt][2];
            s[nt][3] = __expf(s[nt][3]); sumB += s[nt][3];
        }
        sumA += __shfl_xor_sync(0xffffffff, sumA, 1);
        sumA += __shfl_xor_sync(0xffffffff, sumA, 2);
        sumB += __shfl_xor_sync(0xffffffff, sumB, 1);
        sumB += __shfl_xor_sync(0xffffffff, sumB, 2);
        float invA = 1.0f / sumA, invB = 1.0f / sumB;
        #pragma unroll
        for (int nt = 0; nt < 7; ++nt) {
            s[nt][0] *= invA; s[nt][1] *= invA;
            s[nt][2] *= invB; s[nt][3] *= invB;
        }

        uint32_t pf[4][4];
        #pragma unroll
        for (int kt = 0; kt < 4; ++kt) {
            int nt0 = 2 * kt, nt1 = 2 * kt + 1;
            pf[kt][0] = pack_bf16x2(s[nt0][0], s[nt0][1]);
            pf[kt][1] = pack_bf16x2(s[nt0][2], s[nt0][3]);
            if (nt1 < 7) {
                pf[kt][2] = pack_bf16x2(s[nt1][0], s[nt1][1]);
                pf[kt][3] = pack_bf16x2(s[nt1][2], s[nt1][3]);
            } else {
                pf[kt][2] = 0u; pf[kt][3] = 0u;
            }
        }

        float o[4][4];
        #pragma unroll
        for (int dt = 0; dt < 4; ++dt)
            #pragma unroll
            for (int q = 0; q < 4; ++q) o[dt][q] = 0.f;
        #pragma unroll
        for (int kt = 0; kt < 4; ++kt) {
            uint32_t vb[2][4];
            #pragma unroll
            for (int dp = 0; dp < 2; ++dp)
                ldm_x4_t(vb[dp], baseV + (uint32_t)(kt * 16 * (AQKV * 2) + dp * 32));
            #pragma unroll
            for (int dt = 0; dt < 4; ++dt)
                mma_bf16(o[dt], pf[kt], vb[dt >> 1][2 * (dt & 1)], vb[dt >> 1][2 * (dt & 1) + 1]);
        }

        // store O into own dead Q slice — race-free
        #pragma unroll
        for (int dt = 0; dt < 4; ++dt) {
            int col = hd * 32 + dt * 8 + 2 * tg;
            *(__nv_bfloat162*)&sQKV[rA * AQKV + col] = __floats2bfloat162_rn(o[dt][0], o[dt][1]);
            *(__nv_bfloat162*)&sQKV[rB * AQKV + col] = __floats2bfloat162_rn(o[dt][2], o[dt][3]);
        }
    }
    __syncthreads();   // all O in smem; K/V regions now dead

    // ---------- phase 2: proj ----------
    for (int e = tid; e < 2048; e += 256) {
        int j = e >> 4, kq = e & 15;
        *(uint4*)&sQKV[(j & 63) * AQKV + 128 + ((j >> 6) << 7) + kq * 8] =
            *(const uint4*)(g_wproj + j * 128 + kq * 8);
    }
    __syncthreads();

    int warp_m = half, warp_n = hd;
    uint32_t baseA2 = sq + (uint32_t)((warp_m * 32 + lrow) * (AQKV * 2) + lsel);
    uint32_t baseB2 = sq + (uint32_t)((((warp_n * 32) & 63) + lrow) * (AQKV * 2)
                                      + (128 + ((warp_n >> 1) << 7)) * 2 + lsel);

    float pc[2][4][4];
    #pragma unroll
    for (int mt2 = 0; mt2 < 2; ++mt2)
        #pragma unroll
        for (int j = 0; j < 4; ++j)
            #pragma unroll
            for (int q = 0; q < 4; ++q) pc[mt2][j][q] = 0.f;

    #pragma unroll
    for (int k0 = 0; k0 < 128; k0 += 16) {
        uint32_t af[2][4], bbp[2][4];
        #pragma unroll
        for (int mt2 = 0; mt2 < 2; ++mt2)
            ldm_x4(af[mt2], baseA2 + (uint32_t)(mt2 * 16 * (AQKV * 2) + k0 * 2));
        #pragma unroll
        for (int p = 0; p < 2; ++p)
            ldm_x4(bbp[p], baseB2 + (uint32_t)(p * 16 * (AQKV * 2) + k0 * 2));
        #pragma unroll
        for (int mt2 = 0; mt2 < 2; ++mt2)
            #pragma unroll
            for (int p = 0; p < 2; ++p) {
                mma_bf16(pc[mt2][2 * p],     af[mt2], bbp[p][0], bbp[p][2]);
                mma_bf16(pc[mt2][2 * p + 1], af[mt2], bbp[p][1], bbp[p][3]);
            }
    }

    __nv_bfloat16* ow = g_owin + (size_t)wi * Nwin * 128;
    #pragma unroll
    for (int j = 0; j < 4; ++j) {
        int col = warp_n * 32 + j * 8 + 2 * tg;
        float b0v = proj_b[col], b1v = proj_b[col + 1];
        #pragma unroll
        for (int mt2 = 0; mt2 < 2; ++mt2) {
            int row = warp_m * 32 + mt2 * 16 + g;
            if (row < Nwin)
                *(__nv_bfloat162*)&ow[(size_t)row * 128 + col] =
                    __floats2bfloat162_rn(pc[mt2][j][0] + b0v, pc[mt2][j][1] + b1v);
            if (row + 8 < Nwin)
                *(__nv_bfloat162*)&ow[(size_t)(row + 8) * 128 + col] =
                    __floats2bfloat162_rn(pc[mt2][j][2] + b0v, pc[mt2][j][3] + b1v);
        }
    }
}

// ---------------- K5: window reverse + unshift + residual (vectorized) ----------------
__global__ void reverse_kernel(const float* __restrict__ x,
                               float* __restrict__ out) {
    __shared__ float s2[56 * 132];   // [wl][c]
    int h = blockIdx.x, half = blockIdx.y, b = blockIdx.z;
    int w0 = half * 56;
    int tid = threadIdx.x;

    int h2 = h - SHIFT; if (h2 < 0) h2 += Hdim;
    int whh = h2 / Mwin, rr = h2 % Mwin;

    for (int e = tid; e < 56 * 16; e += 256) {
        int wl = e >> 4, j = e & 15;
        int w = w0 + wl;
        int w2 = w - SHIFT; if (w2 < 0) w2 += Wdim;
        int wi = b * NWIMG + whh * NHw + (w2 / Mwin);
        int n  = rr * Mwin + (w2 % Mwin);
        uint4 raw = *(const uint4*)&g_owin[((size_t)wi * Nwin + n) * 128 + j * 8];
        __nv_bfloat162 p[4]; *(uint4*)p = raw;
        float2 f0 = __bfloat1622float2(p[0]);
        float2 f1 = __bfloat1622float2(p[1]);
        float2 f2 = __bfloat1622float2(p[2]);
        float2 f3 = __bfloat1622float2(p[3]);
        *(float4*)&s2[wl * 132 + j * 8]     = make_float4(f0.x, f0.y, f1.x, f1.y);
        *(float4*)&s2[wl * 132 + j * 8 + 4] = make_float4(f2.x, f2.y, f3.x, f3.y);
    }
    __syncthreads();

    size_t base = (size_t)b * Cdim * (Hdim * Wdim) + (size_t)h * Wdim + w0;
    for (int e = tid; e < 128 * 14; e += 256) {
        int c = e / 14, wq = (e % 14) * 4;
        size_t gi = base + (size_t)c * (Hdim * Wdim) + wq;
        float4 xv = *(const float4*)&x[gi];
        float4 o;
        o.x = xv.x + s2[(wq + 0) * 132 + c];
        o.y = xv.y + s2[(wq + 1) * 132 + c];
        o.z = xv.z + s2[(wq + 2) * 132 + c];
        o.w = xv.w + s2[(wq + 3) * 132 + c];
        *(float4*)&out[gi] = o;
    }
}

// ---------------- launch ----------------
extern "C" void kernel_launch(void* const* d_in, const int* in_sizes, int n_in,
                              void* d_out, int out_size) {
    const float* x          = (const float*)d_in[0];
    const float* norm_w     = (const float*)d_in[1];
    const float* norm_b     = (const float*)d_in[2];
    const float* qkv_w      = (const float*)d_in[3];
    const float* qkv_b      = (const float*)d_in[4];
    const float* proj_w     = (const float*)d_in[5];
    const float* proj_b     = (const float*)d_in[6];
    const float* bias_table = (const float*)d_in[7];
    const int*   rel_index  = (const int*)  d_in[8];
    const float* attn_mask  = (const float*)d_in[9];
    float* out = (float*)d_out;

    cudaFuncSetAttribute(gemm_qkv_kernel, cudaFuncAttributeMaxDynamicSharedMemorySize, GQ_SMEM);
    cudaFuncSetAttribute(attn_kernel,     cudaFuncAttributeMaxDynamicSharedMemorySize, ATTN_SMEM);

    ln_prep_kernel<<<dim3(Hdim, 2, Bsz + PC_ZSL), 256>>>(x, norm_w, norm_b,
                                                         qkv_w, proj_w, attn_mask,
                                                         bias_table, rel_index);
    gemm_qkv_kernel<<<NTOK / 128, 256, GQ_SMEM>>>(qkv_b);
    attn_kernel<<<NWTOT, 256, ATTN_SMEM>>>(proj_b);
    reverse_kernel<<<dim3(Hdim, 2, Bsz), 256>>>(x, out);
}

// round 17
// speedup vs baseline: 1.4431x; 1.0130x over previous
#include <cuda_runtime.h>
#include <cuda_bf16.h>
#include <cstdint>

#define Bsz   32
#define Cdim  128
#define Hdim  112
#define Wdim  112
#define Mwin  7
#define Nwin  49
#define NHw   16
#define NWIMG 256
#define NWTOT 8192
#define HEADS 4
#define DHEAD 32
#define SHIFT 3
#define NTOK  (NWTOT * Nwin)          // 401408
#define QSCALE 0.17677669529663687f   // 1/sqrt(32)

// ---------------- scratch (device globals; no allocation) ----------------
__device__ __nv_bfloat16 g_win [(size_t)NTOK * 128];   // LN+shifted tokens (bf16)
__device__ __nv_bfloat16 g_qkv [(size_t)NTOK * 384];   // QKV (bf16, Q pre-scaled)
__device__ __nv_bfloat16 g_owin[(size_t)NTOK * 128];   // proj output (bf16, bias added)
__device__ __nv_bfloat16 g_wqkv [384 * 128];           // bf16 weights [j][k]
__device__ __nv_bfloat16 g_wproj[128 * 128];
__device__ __nv_bfloat16 g_cmb  [(size_t)NWIMG * HEADS * 64 * 56];  // bias+mask combined

// ---------------- helpers ----------------
__device__ __forceinline__ uint32_t smem_u32(const void* p) {
    uint32_t a;
    asm("{ .reg .u64 t; cvta.to.shared.u64 t, %1; cvt.u32.u64 %0, t; }" : "=r"(a) : "l"(p));
    return a;
}
__device__ __forceinline__ void ldm_x4(uint32_t r[4], uint32_t addr) {
    asm volatile("ldmatrix.sync.aligned.m8n8.x4.shared.b16 {%0,%1,%2,%3}, [%4];"
        : "=r"(r[0]), "=r"(r[1]), "=r"(r[2]), "=r"(r[3]) : "r"(addr));
}
__device__ __forceinline__ void ldm_x4_t(uint32_t r[4], uint32_t addr) {
    asm volatile("ldmatrix.sync.aligned.m8n8.x4.trans.shared.b16 {%0,%1,%2,%3}, [%4];"
        : "=r"(r[0]), "=r"(r[1]), "=r"(r[2]), "=r"(r[3]) : "r"(addr));
}
__device__ __forceinline__ void mma_bf16(float c[4], const uint32_t a[4],
                                         uint32_t b0, uint32_t b1) {
    asm volatile("mma.sync.aligned.m16n8k16.row.col.f32.bf16.bf16.f32 "
        "{%0,%1,%2,%3}, {%4,%5,%6,%7}, {%8,%9}, {%0,%1,%2,%3};"
        : "+f"(c[0]), "+f"(c[1]), "+f"(c[2]), "+f"(c[3])
        : "r"(a[0]), "r"(a[1]), "r"(a[2]), "r"(a[3]), "r"(b0), "r"(b1));
}
__device__ __forceinline__ uint32_t pack_bf16x2(float a, float b) {
    __nv_bfloat162 t = __floats2bfloat162_rn(a, b);
    return *(uint32_t*)&t;
}

#define LDAB 272          // GEMM smem row stride in bytes (136 bf16)
#define TILE_B 34816      // 128 * 272

#define PREP_N (384 * 128 + 128 * 128)
#define CMB_N  (NWIMG * HEADS * 64 * 56)
#define PC_TOTAL (PREP_N + CMB_N)                 // 1900544
#define PC_CTAS  ((PC_TOTAL + 255) / 256)         // 7424
#define PC_ZSL   ((PC_CTAS + Hdim * 2 - 1) / (Hdim * 2))   // 34 extra z-slices

// ---------------- K1: LayerNorm+window (z < Bsz)  |  prep+cmb (z >= Bsz) ----------------
// smem [row w][128 c] stride 132; column blocks of 8 floats rotated by (row>>2)&15
#define RS 132
__global__ void ln_prep_kernel(const float* __restrict__ x,
                               const float* __restrict__ nw,
                               const float* __restrict__ nb,
                               const float* __restrict__ qkv_w,
                               const float* __restrict__ proj_w,
                               const float* __restrict__ attn_mask,
                               const float* __restrict__ bias_table,
                               const int*   __restrict__ rel_index) {
    __shared__ float s[56 * RS];
    int tid = threadIdx.x;

    if (blockIdx.z >= Bsz) {
        // ---- prep + cmb branch (exits before any barrier) ----
        int pb = (blockIdx.z - Bsz) * (Hdim * 2) + blockIdx.x * 2 + blockIdx.y;
        int i = pb * 256 + tid;
        if (i < PREP_N) {
            if (i < 384 * 128) g_wqkv[i] = __float2bfloat16_rn(qkv_w[i]);
            else               g_wproj[i - 384 * 128] = __float2bfloat16_rn(proj_w[i - 384 * 128]);
            return;
        }
        i -= PREP_N;
        if (i >= CMB_N) return;
        int m = i % 56; int t = i / 56;
        int n = t & 63; t >>= 6;
        int hd = t & 3; int wimg = t >> 2;
        float v;
        if (n >= Nwin)      v = 0.f;
        else if (m >= Nwin) v = -30000.f;
        else v = bias_table[rel_index[n * Nwin + m] * HEADS + hd]
               + attn_mask[((size_t)wimg * Nwin + n) * Nwin + m];
        g_cmb[i] = __float2bfloat16_rn(v);
        return;
    }

    // ---- LayerNorm branch ----
    int h = blockIdx.x, half = blockIdx.y, b = blockIdx.z;
    int w0 = half * 56;

    const float* xp = x + (size_t)b * Cdim * (Hdim * Wdim) + (size_t)h * Wdim + w0;
    for (int e = tid; e < 128 * 14; e += 256) {
        int c = e / 14, w4 = (e % 14) * 4;
        float4 v = *(const float4*)(xp + (size_t)c * (Hdim * Wdim) + w4);
        float vv[4] = {v.x, v.y, v.z, v.w};
        int jj = c >> 3, co = c & 7;
        #pragma unroll
        for (int i2 = 0; i2 < 4; ++i2) {
            int row = w4 + i2;
            int jr = (jj + (row >> 2)) & 15;
            s[row * RS + jr * 8 + co] = vv[i2];
        }
    }
    __syncthreads();

    int warp = tid >> 5, lane = tid & 31;
    for (int wl = warp; wl < 56; wl += 8) {
        int rot = (wl >> 2) & 15;
        int jr = (((lane >> 1) + rot) & 15);
        float4 v = *(const float4*)&s[wl * RS + jr * 8 + (lane & 1) * 4];
        float sum = v.x + v.y + v.z + v.w;
        float sq  = v.x * v.x + v.y * v.y + v.z * v.z + v.w * v.w;
        #pragma unroll
        for (int o = 16; o > 0; o >>= 1) {
            sum += __shfl_xor_sync(0xffffffff, sum, o);
            sq  += __shfl_xor_sync(0xffffffff, sq,  o);
        }
        float mu  = sum * (1.0f / 128.0f);
        float var = sq * (1.0f / 128.0f) - mu * mu;
        float inv = rsqrtf(var + 1e-5f);

        int c0 = lane * 4;     // logical column of this lane's float4 (block lane>>1, half lane&1)
        float4 g  = *(const float4*)&nw[c0];
        float4 be = *(const float4*)&nb[c0];
        __align__(8) __nv_bfloat162 o2[2];
        o2[0] = __floats2bfloat162_rn((v.x - mu) * inv * g.x + be.x,
                                      (v.y - mu) * inv * g.y + be.y);
        o2[1] = __floats2bfloat162_rn((v.z - mu) * inv * g.z + be.z,
                                      (v.w - mu) * inv * g.w + be.w);

        int ws = w0 + wl;
        int hd = h - SHIFT;  if (hd < 0) hd += Hdim;
        int wd = ws - SHIFT; if (wd < 0) wd += Wdim;
        int wi = b * NWIMG + (hd / Mwin) * NHw + (wd / Mwin);
        int n  = (hd % Mwin) * Mwin + (wd % Mwin);
        *(uint2*)&g_win[((size_t)wi * Nwin + n) * 128 + c0] = *(uint2*)o2;
    }
}

// ---------------- K2: QKV GEMM (mma.sync bf16), 8 warps of 64x32 ----------------
#define GQ_SMEM (3 * TILE_B)
__global__ __launch_bounds__(256, 2) void gemm_qkv_kernel(const float* __restrict__ qkv_b) {
    extern __shared__ __align__(16) char sm[];
    char* sA = sm;
    char* sB = sm + TILE_B;
    char* sC = sm + 2 * TILE_B;

    int tid = threadIdx.x, wid = tid >> 5, lane = tid & 31;
    int warp_m = wid >> 2, warp_n = wid & 3;

    const __nv_bfloat16* A = g_win + (size_t)blockIdx.x * (128 * 128);
    for (int e = tid; e < 2048; e += 256) {
        int r = e >> 4, j = e & 15;
        *(uint4*)(sA + r * LDAB + j * 16) = *(const uint4*)(A + r * 128 + j * 8);
    }
    for (int e = tid; e < 2048; e += 256) {
        int r = e >> 4, j = e & 15;
        *(uint4*)(sB + r * LDAB + j * 16) = *(const uint4*)(g_wqkv + r * 128 + j * 8);
    }
    __syncthreads();

    uint32_t pA = smem_u32(sA) + (uint32_t)((warp_m * 64 + (lane & 15)) * LDAB + ((lane >> 4) << 4));
    uint32_t pB = smem_u32(sB) + (uint32_t)((warp_n * 32 + (lane & 15)) * LDAB + ((lane >> 4) << 4));
    size_t row0 = (size_t)blockIdx.x * 128;
    int g = lane >> 2, tg = lane & 3;

    #pragma unroll 1
    for (int jb = 0; jb < 3; ++jb) {
        float c[4][4][4];
        #pragma unroll
        for (int mt = 0; mt < 4; ++mt)
            #pragma unroll
            for (int nt = 0; nt < 4; ++nt)
                #pragma unroll
                for (int q = 0; q < 4; ++q) c[mt][nt][q] = 0.f;

        #pragma unroll
        for (int k0 = 0; k0 < 128; k0 += 16) {
            uint32_t a[4][4], bb[2][4];
            #pragma unroll
            for (int mt = 0; mt < 4; ++mt)
                ldm_x4(a[mt], pA + mt * (16 * LDAB) + k0 * 2);
            #pragma unroll
            for (int p = 0; p < 2; ++p)
                ldm_x4(bb[p], pB + p * (16 * LDAB) + k0 * 2);
            #pragma unroll
            for (int mt = 0; mt < 4; ++mt)
                #pragma unroll
                for (int nt = 0; nt < 4; ++nt)
                    mma_bf16(c[mt][nt], a[mt], bb[nt >> 1][nt & 1], bb[nt >> 1][2 + (nt & 1)]);
        }

        float s = (jb == 0) ? QSCALE : 1.0f;
        #pragma unroll
        for (int nt = 0; nt < 4; ++nt) {
            int col = warp_n * 32 + nt * 8 + 2 * tg;
            float b0v = qkv_b[jb * 128 + col];
            float b1v = qkv_b[jb * 128 + col + 1];
            #pragma unroll
            for (int mt = 0; mt < 4; ++mt) {
                int row = warp_m * 64 + mt * 16 + g;
                __nv_bfloat162 lo = __floats2bfloat162_rn((c[mt][nt][0] + b0v) * s,
                                                          (c[mt][nt][1] + b1v) * s);
                __nv_bfloat162 hi = __floats2bfloat162_rn((c[mt][nt][2] + b0v) * s,
                                                          (c[mt][nt][3] + b1v) * s);
                *(__nv_bfloat162*)(sC + row * LDAB + col * 2) = lo;
                *(__nv_bfloat162*)(sC + (row + 8) * LDAB + col * 2) = hi;
            }
        }
        __syncthreads();

        if (jb < 2) {
            const __nv_bfloat16* Bn = g_wqkv + (size_t)(jb + 1) * 128 * 128;
            for (int e = tid; e < 2048; e += 256) {
                int r = e >> 4, j = e & 15;
                *(uint4*)(sB + r * LDAB + j * 16) = *(const uint4*)(Bn + r * 128 + j * 8);
            }
        }
        for (int e = tid; e < 2048; e += 256) {
            int r = e >> 4, j = e & 15;
            *(uint4*)(g_qkv + (row0 + r) * 384 + jb * 128 + j * 8) =
                *(uint4*)(sC + r * LDAB + j * 16);
        }
        __syncthreads();
    }
}

// ---------------- K3: fused window attention + proj (mma.sync), r13 config ----------------
#define AQKV 392
#define ATTN_SMEM (64 * AQKV * 2)   // 50176 B -> 4 CTAs/SM
__global__ __launch_bounds__(256, 4) void attn_kernel(const float* __restrict__ proj_b) {
    extern __shared__ __align__(16) __nv_bfloat16 smb[];
    __nv_bfloat16* sQKV = smb;

    int wi = blockIdx.x, wimg = wi & (NWIMG - 1), tid = threadIdx.x;
    int wid = tid >> 5, lane = tid & 31;

    const __nv_bfloat16* src = g_qkv + (size_t)wi * Nwin * 384;
    for (int e = tid; e < Nwin * 48; e += 256) {
        int n = e / 48, j = e % 48;
        *(uint4*)&sQKV[n * AQKV + j * 8] = *(const uint4*)(src + n * 384 + j * 8);
    }
    for (int e = tid; e < 15 * 49; e += 256) {
        int r = 49 + e / 49, j = e % 49;
        *(uint4*)&sQKV[r * AQKV + j * 8] = make_uint4(0, 0, 0, 0);
    }
    __syncthreads();

    int hd = wid & 3, half = wid >> 2;
    int g = lane >> 2, tg = lane & 3;
    uint32_t sq = smem_u32(sQKV);
    int lrow = lane & 15, lsel = (lane >> 4) << 4;
    uint32_t baseQ = sq + (uint32_t)(lrow * (AQKV * 2) + (hd * 32) * 2 + lsel);
    uint32_t baseK = sq + (uint32_t)(lrow * (AQKV * 2) + (128 + hd * 32) * 2 + lsel);
    uint32_t baseV = sq + (uint32_t)(lrow * (AQKV * 2) + (256 + hd * 32) * 2 + lsel);

    const __nv_bfloat162* cm =
        (const __nv_bfloat162*)(g_cmb + (size_t)(wimg * HEADS + hd) * 64 * 56);

    // ---------- phase 1: attention ----------
    #pragma unroll
    for (int mi = 0; mi < 2; ++mi) {
        int mt = half * 2 + mi;
        uint32_t qf[2][4];
        #pragma unroll
        for (int kt = 0; kt < 2; ++kt)
            ldm_x4(qf[kt], baseQ + (uint32_t)(mt * 16 * (AQKV * 2) + kt * 32));

        int rA = mt * 16 + g, rB = rA + 8;
        float s[7][4];
        #pragma unroll
        for (int nt = 0; nt < 7; ++nt) {
            float2 fa = __bfloat1622float2(cm[(rA * 56 + nt * 8 + 2 * tg) >> 1]);
            float2 fb = __bfloat1622float2(cm[(rB * 56 + nt * 8 + 2 * tg) >> 1]);
            s[nt][0] = fa.x; s[nt][1] = fa.y; s[nt][2] = fb.x; s[nt][3] = fb.y;
        }
        #pragma unroll
        for (int kt = 0; kt < 2; ++kt) {
            #pragma unroll
            for (int ntp = 0; ntp < 4; ++ntp) {
                uint32_t kb[4];
                ldm_x4(kb, baseK + (uint32_t)(ntp * 16 * (AQKV * 2) + kt * 32));
                mma_bf16(s[2 * ntp], qf[kt], kb[0], kb[2]);
                if (ntp < 3) mma_bf16(s[2 * ntp + 1], qf[kt], kb[1], kb[3]);
            }
        }

        // softmax without max subtraction (logits bounded; pads -> exp(-3e4)=0)
        float sumA = 0.f, sumB = 0.f;
        #pragma unroll
        for (int nt = 0; nt < 7; ++nt) {
            s[nt][0] = __expf(s[nt][0]); sumA += s[nt][0];
            s[nt][1] = __expf(s[nt][1]); sumA += s[nt][1];
            s[nt][2] = __expf(s[nt][2]); sumB += s[nt][2];
            s[nt][3] = __expf(s[nt][3]); sumB += s[nt][3];
        }
        sumA += __shfl_xor_sync(0xffffffff, sumA, 1);
        sumA += __shfl_xor_sync(0xffffffff, sumA, 2);
        sumB += __shfl_xor_sync(0xffffffff, sumB, 1);
        sumB += __shfl_xor_sync(0xffffffff, sumB, 2);
        float invA = 1.0f / sumA, invB = 1.0f / sumB;
        #pragma unroll
        for (int nt = 0; nt < 7; ++nt) {
            s[nt][0] *= invA; s[nt][1] *= invA;
            s[nt][2] *= invB; s[nt][3] *= invB;
        }

        uint32_t pf[4][4];
        #pragma unroll
        for (int kt = 0; kt < 4; ++kt) {
            int nt0 = 2 * kt, nt1 = 2 * kt + 1;
            pf[kt][0] = pack_bf16x2(s[nt0][0], s[nt0][1]);
            pf[kt][1] = pack_bf16x2(s[nt0][2], s[nt0][3]);
            if (nt1 < 7) {
                pf[kt][2] = pack_bf16x2(s[nt1][0], s[nt1][1]);
                pf[kt][3] = pack_bf16x2(s[nt1][2], s[nt1][3]);
            } else {
                pf[kt][2] = 0u; pf[kt][3] = 0u;
            }
        }

        float o[4][4];
        #pragma unroll
        for (int dt = 0; dt < 4; ++dt)
            #pragma unroll
            for (int q = 0; q < 4; ++q) o[dt][q] = 0.f;
        #pragma unroll
        for (int kt = 0; kt < 4; ++kt) {
            uint32_t vb[2][4];
            #pragma unroll
            for (int dp = 0; dp < 2; ++dp)
                ldm_x4_t(vb[dp], baseV + (uint32_t)(kt * 16 * (AQKV * 2) + dp * 32));
            #pragma unroll
            for (int dt = 0; dt < 4; ++dt)
                mma_bf16(o[dt], pf[kt], vb[dt >> 1][2 * (dt & 1)], vb[dt >> 1][2 * (dt & 1) + 1]);
        }

        // store O into own dead Q slice — race-free
        #pragma unroll
        for (int dt = 0; dt < 4; ++dt) {
            int col = hd * 32 + dt * 8 + 2 * tg;
            *(__nv_bfloat162*)&sQKV[rA * AQKV + col] = __floats2bfloat162_rn(o[dt][0], o[dt][1]);
            *(__nv_bfloat162*)&sQKV[rB * AQKV + col] = __floats2bfloat162_rn(o[dt][2], o[dt][3]);
        }
    }
    __syncthreads();   // all O in smem; K/V regions now dead

    // ---------- phase 2: proj ----------
    for (int e = tid; e < 2048; e += 256) {
        int j = e >> 4, kq = e & 15;
        *(uint4*)&sQKV[(j & 63) * AQKV + 128 + ((j >> 6) << 7) + kq * 8] =
            *(const uint4*)(g_wproj + j * 128 + kq * 8);
    }
    __syncthreads();

    int warp_m = half, warp_n = hd;
    uint32_t baseA2 = sq + (uint32_t)((warp_m * 32 + lrow) * (AQKV * 2) + lsel);
    uint32_t baseB2 = sq + (uint32_t)((((warp_n * 32) & 63) + lrow) * (AQKV * 2)
                                      + (128 + ((warp_n >> 1) << 7)) * 2 + lsel);

    float pc[2][4][4];
    #pragma unroll
    for (int mt2 = 0; mt2 < 2; ++mt2)
        #pragma unroll
        for (int j = 0; j < 4; ++j)
            #pragma unroll
            for (int q = 0; q < 4; ++q) pc[mt2][j][q] = 0.f;

    #pragma unroll
    for (int k0 = 0; k0 < 128; k0 += 16) {
        uint32_t af[2][4], bbp[2][4];
        #pragma unroll
        for (int mt2 = 0; mt2 < 2; ++mt2)
            ldm_x4(af[mt2], baseA2 + (uint32_t)(mt2 * 16 * (AQKV * 2) + k0 * 2));
        #pragma unroll
        for (int p = 0; p < 2; ++p)
            ldm_x4(bbp[p], baseB2 + (uint32_t)(p * 16 * (AQKV * 2) + k0 * 2));
        #pragma unroll
        for (int mt2 = 0; mt2 < 2; ++mt2)
            #pragma unroll
            for (int p = 0; p < 2; ++p) {
                mma_bf16(pc[mt2][2 * p],     af[mt2], bbp[p][0], bbp[p][2]);
                mma_bf16(pc[mt2][2 * p + 1], af[mt2], bbp[p][1], bbp[p][3]);
            }
    }

    __nv_bfloat16* ow = g_owin + (size_t)wi * Nwin * 128;
    #pragma unroll
    for (int j = 0; j < 4; ++j) {
        int col = warp_n * 32 + j * 8 + 2 * tg;
        float b0v = proj_b[col], b1v = proj_b[col + 1];
        #pragma unroll
        for (int mt2 = 0; mt2 < 2; ++mt2) {
            int row = warp_m * 32 + mt2 * 16 + g;
            if (row < Nwin)
                *(__nv_bfloat162*)&ow[(size_t)row * 128 + col] =
                    __floats2bfloat162_rn(pc[mt2][j][0] + b0v, pc[mt2][j][1] + b1v);
            if (row + 8 < Nwin)
                *(__nv_bfloat162*)&ow[(size_t)(row + 8) * 128 + col] =
                    __floats2bfloat162_rn(pc[mt2][j][2] + b0v, pc[mt2][j][3] + b1v);
        }
    }
}

// ---------------- K5: window reverse + unshift + residual (rot-swizzled smem) ----------------
__global__ void reverse_kernel(const float* __restrict__ x,
                               float* __restrict__ out) {
    __shared__ float s2[56 * 132];   // [wl][c], blocks of 8 rotated by (wl>>2)&15
    int h = blockIdx.x, half = blockIdx.y, b = blockIdx.z;
    int w0 = half * 56;
    int tid = threadIdx.x;

    int h2 = h - SHIFT; if (h2 < 0) h2 += Hdim;
    int whh = h2 / Mwin, rr = h2 % Mwin;

    // phase 1: uint4 gathers from g_owin (block j of 8 c's), rotated float4 smem stores
    for (int e = tid; e < 56 * 16; e += 256) {
        int wl = e >> 4, j = e & 15;
        int w = w0 + wl;
        int w2 = w - SHIFT; if (w2 < 0) w2 += Wdim;
        int wi = b * NWIMG + whh * NHw + (w2 / Mwin);
        int n  = rr * Mwin + (w2 % Mwin);
        uint4 raw = *(const uint4*)&g_owin[((size_t)wi * Nwin + n) * 128 + j * 8];
        __nv_bfloat162 p[4]; *(uint4*)p = raw;
        float2 f0 = __bfloat1622float2(p[0]);
        float2 f1 = __bfloat1622float2(p[1]);
        float2 f2 = __bfloat1622float2(p[2]);
        float2 f3 = __bfloat1622float2(p[3]);
        int jr = (j + (wl >> 2)) & 15;
        *(float4*)&s2[wl * 132 + jr * 8]     = make_float4(f0.x, f0.y, f1.x, f1.y);
        *(float4*)&s2[wl * 132 + jr * 8 + 4] = make_float4(f2.x, f2.y, f3.x, f3.y);
    }
    __syncthreads();

    // phase 2: float4 x loads + out stores; rotated scalar smem reads
    size_t base = (size_t)b * Cdim * (Hdim * Wdim) + (size_t)h * Wdim + w0;
    for (int e = tid; e < 128 * 14; e += 256) {
        int c = e / 14, wq = (e % 14) * 4;
        size_t gi = base + (size_t)c * (Hdim * Wdim) + wq;
        float4 xv = *(const float4*)&x[gi];
        int jj = c >> 3, co = c & 7;
        float4 o;
        {
            int r0 = wq;     int j0 = (jj + (r0 >> 2)) & 15; o.x = xv.x + s2[r0 * 132 + j0 * 8 + co];
            int r1 = wq + 1; int j1 = (jj + (r1 >> 2)) & 15; o.y = xv.y + s2[r1 * 132 + j1 * 8 + co];
            int r2 = wq + 2; int j2 = (jj + (r2 >> 2)) & 15; o.z = xv.z + s2[r2 * 132 + j2 * 8 + co];
            int r3 = wq + 3; int j3 = (jj + (r3 >> 2)) & 15; o.w = xv.w + s2[r3 * 132 + j3 * 8 + co];
        }
        *(float4*)&out[gi] = o;
    }
}

// ---------------- launch ----------------
extern "C" void kernel_launch(void* const* d_in, const int* in_sizes, int n_in,
                              void* d_out, int out_size) {
    const float* x          = (const float*)d_in[0];
    const float* norm_w     = (const float*)d_in[1];
    const float* norm_b     = (const float*)d_in[2];
    const float* qkv_w      = (const float*)d_in[3];
    const float* qkv_b      = (const float*)d_in[4];
    const float* proj_w     = (const float*)d_in[5];
    const float* proj_b     = (const float*)d_in[6];
    const float* bias_table = (const float*)d_in[7];
    const int*   rel_index  = (const int*)  d_in[8];
    const float* attn_mask  = (const float*)d_in[9];
    float* out = (float*)d_out;

    cudaFuncSetAttribute(gemm_qkv_kernel, cudaFuncAttributeMaxDynamicSharedMemorySize, GQ_SMEM);
    cudaFuncSetAttribute(attn_kernel,     cudaFuncAttributeMaxDynamicSharedMemorySize, ATTN_SMEM);

    ln_prep_kernel<<<dim3(Hdim, 2, Bsz + PC_ZSL), 256>>>(x, norm_w, norm_b,
                                                         qkv_w, proj_w, attn_mask,
                                                         bias_table, rel_index);
    gemm_qkv_kernel<<<NTOK / 128, 256, GQ_SMEM>>>(qkv_b);
    attn_kernel<<<NWTOT, 256, ATTN_SMEM>>>(proj_b);
    reverse_kernel<<<dim3(Hdim, 2, Bsz), 256>>>(x, out);
}